// round 10
// baseline (speedup 1.0000x reference)
#include <cuda_runtime.h>

#define TW 32
#define TH 64
#define HALO 5
#define RW (TW + 2*HALO)      // 42
#define RH (TH + 2*HALO)      // 74
#define NT 512
#define IMG 512
#define PLANE (IMG*IMG)

#define SSIM_C1 0.0001f
#define SSIM_C2 0.0009f

// smem: float2 raw[RH*RW] (24864 B) + 4 hb planes [RH*TW] (37888 B) = 62752 B
#define RAW_N (RH*RW)
#define HB_N  (RH*TW)
#define SMEM_BYTES (RAW_N*8 + 4*HB_N*4)

// 11-tap gaussian, sigma=1.5, normalized; symmetric
__device__ __forceinline__ constexpr float wk(int k) {
    constexpr float W6[6] = { 0.00102838f, 0.00759876f, 0.03600077f,
                              0.10936078f, 0.21300553f, 0.26601171f };
    return W6[k < 6 ? k : 10 - k];
}

__global__ void __launch_bounds__(NT, 3)
ssim_kernel(const float* __restrict__ x, const float* __restrict__ y,
            float* __restrict__ out)
{
    extern __shared__ float smem[];
    float2* raw = (float2*)smem;            // RH*RW  {x,y}
    float*  hb  = smem + RAW_N*2;           // 4 planes: x, y, x2+y2, xy

    const int tid   = threadIdx.x;
    const int bx    = blockIdx.x;           // 0..15
    const int by    = blockIdx.y;           // 0..7
    const int plane = blockIdx.z;           // 0..47

    const float* __restrict__ xp = x + (size_t)plane * PLANE;
    const float* __restrict__ yp = y + (size_t)plane * PLANE;

    const int gx0 = bx * TW - HALO;
    const int gy0 = by * TH - HALO;

    const bool interior = (gx0 >= 0) & (gy0 >= 0) &
                          (gx0 + RW <= IMG) & (gy0 + RH <= IMG);

    // ---------------- Stage 1: gmem -> smem raw tile ----------------------
    if (interior) {
        // pair-granular: 21 column-pairs x 74 rows = 1554 tasks, divless walk.
        // gmem side: scalar LDG.32 (halo origin is odd -> no 8B alignment);
        // smem side: one STS.128 per pair.
        int r = tid / 21;
        int c = tid - r * 21;                // pair index 0..20
        #pragma unroll 1
        while (r < RH) {
            const float* xq = xp + (gy0 + r) * IMG + gx0 + 2*c;
            const float* yq = yp + (gy0 + r) * IMG + gx0 + 2*c;
            float x0 = __ldg(xq);
            float x1 = __ldg(xq + 1);
            float y0 = __ldg(yq);
            float y1 = __ldg(yq + 1);
            *(float4*)&raw[r * RW + 2*c] = make_float4(x0, y0, x1, y1);
            // advance by 512 tasks = 24*21 + 8
            r += 24; c += 8;
            if (c >= 21) { c -= 21; r += 1; }
        }
    } else {
        #pragma unroll 1
        for (int i = tid; i < RAW_N; i += NT) {
            int r = i / RW;
            int c = i - r * RW;
            int gr = gy0 + r, gc = gx0 + c;
            float xv = 0.f, yv = 0.f;
            if ((unsigned)gr < (unsigned)IMG && (unsigned)gc < (unsigned)IMG) {
                int off = gr * IMG + gc;
                xv = __ldg(xp + off);
                yv = __ldg(yp + off);
            }
            raw[i] = make_float2(xv, yv);
        }
    }
    __syncthreads();

    // ---------------- Stage 2: horizontal 11-tap, 4-col register block ----
    // tasks: RH rows * 8 groups of 4 cols = 592
    for (int t = tid; t < RH*(TW/4); t += NT) {
        const int row = t >> 3;
        const int g   = (t & 7) * 4;
        // raw row start is 16B-aligned: (row*RW + g) even in float2 units
        const float4* rp4 = (const float4*)(raw + row * RW + g);

        float a0[4] = {0,0,0,0};   // hblur(x)
        float a1[4] = {0,0,0,0};   // hblur(y)
        float a2[4] = {0,0,0,0};   // hblur(x^2 + y^2)
        float a3[4] = {0,0,0,0};   // hblur(x*y)

        #pragma unroll
        for (int q = 0; q < 7; ++q) {        // 7 x LDS.128 = 14 taps
            float4 pr = rp4[q];              // {x0,y0,x1,y1} = taps 2q, 2q+1
            #pragma unroll
            for (int h = 0; h < 2; ++h) {
                const int p = 2*q + h;
                float vx = h ? pr.z : pr.x;
                float vy = h ? pr.w : pr.y;
                float s  = fmaf(vy, vy, vx * vx);
                float xy = vx * vy;
                #pragma unroll
                for (int i2 = 0; i2 < 4; ++i2) {
                    int k = p - i2;
                    if (k >= 0 && k <= 10) {
                        a0[i2] = fmaf(vx, wk(k), a0[i2]);
                        a1[i2] = fmaf(vy, wk(k), a1[i2]);
                        a2[i2] = fmaf(s,  wk(k), a2[i2]);
                        a3[i2] = fmaf(xy, wk(k), a3[i2]);
                    }
                }
            }
        }

        const int o = row * TW + g;          // g mult of 4 -> 16B aligned
        *(float4*)&hb[0*HB_N + o] = make_float4(a0[0], a0[1], a0[2], a0[3]);
        *(float4*)&hb[1*HB_N + o] = make_float4(a1[0], a1[1], a1[2], a1[3]);
        *(float4*)&hb[2*HB_N + o] = make_float4(a2[0], a2[1], a2[2], a2[3]);
        *(float4*)&hb[3*HB_N + o] = make_float4(a3[0], a3[1], a3[2], a3[3]);
    }
    __syncthreads();

    // ---------------- Stage 3: vertical 11-tap, 2x2 block, LDS.64 --------
    {
        const int cp = (tid & 15) * 2;       // even column
        const int r0 = (tid >> 4) * 2;       // 0..62 step 2

        float2 b0[2], b1[2], b2[2], b3[2];
        #pragma unroll
        for (int i2 = 0; i2 < 2; ++i2) {
            b0[i2] = make_float2(0.f, 0.f); b1[i2] = make_float2(0.f, 0.f);
            b2[i2] = make_float2(0.f, 0.f); b3[i2] = make_float2(0.f, 0.f);
        }

        const float* hbase = hb + r0 * TW + cp;
        #pragma unroll
        for (int p = 0; p < 12; ++p) {
            const int idx = p * TW;
            float2 h0 = *(const float2*)&hbase[0*HB_N + idx];
            float2 h1 = *(const float2*)&hbase[1*HB_N + idx];
            float2 h2 = *(const float2*)&hbase[2*HB_N + idx];
            float2 h3 = *(const float2*)&hbase[3*HB_N + idx];
            #pragma unroll
            for (int i2 = 0; i2 < 2; ++i2) {
                int k = p - i2;
                if (k >= 0 && k <= 10) {
                    const float w = wk(k);
                    b0[i2].x = fmaf(h0.x, w, b0[i2].x);
                    b0[i2].y = fmaf(h0.y, w, b0[i2].y);
                    b1[i2].x = fmaf(h1.x, w, b1[i2].x);
                    b1[i2].y = fmaf(h1.y, w, b1[i2].y);
                    b2[i2].x = fmaf(h2.x, w, b2[i2].x);
                    b2[i2].y = fmaf(h2.y, w, b2[i2].y);
                    b3[i2].x = fmaf(h3.x, w, b3[i2].x);
                    b3[i2].y = fmaf(h3.y, w, b3[i2].y);
                }
            }
        }

        float* op = out + (size_t)plane * PLANE
                        + (size_t)(by * TH + r0) * IMG
                        + bx * TW + cp;

        #pragma unroll
        for (int i2 = 0; i2 < 2; ++i2) {
            float2 res;
            {
                float mu1 = b0[i2].x, mu2 = b1[i2].x;
                float m12 = mu1*mu2, m11 = mu1*mu1, m22 = mu2*mu2;
                float ssum = b2[i2].x - m11 - m22;
                float s12  = b3[i2].x - m12;
                float num = fmaf(2.f, m12, SSIM_C1) * fmaf(2.f, s12, SSIM_C2);
                float den = (m11 + m22 + SSIM_C1) * (ssum + SSIM_C2);
                res.x = __fdividef(num, den);
            }
            {
                float mu1 = b0[i2].y, mu2 = b1[i2].y;
                float m12 = mu1*mu2, m11 = mu1*mu1, m22 = mu2*mu2;
                float ssum = b2[i2].y - m11 - m22;
                float s12  = b3[i2].y - m12;
                float num = fmaf(2.f, m12, SSIM_C1) * fmaf(2.f, s12, SSIM_C2);
                float den = (m11 + m22 + SSIM_C1) * (ssum + SSIM_C2);
                res.y = __fdividef(num, den);
            }
            *(float2*)(op + (size_t)i2 * IMG) = res;   // STG.64 (cp even -> aligned)
        }
    }
}

extern "C" void kernel_launch(void* const* d_in, const int* in_sizes, int n_in,
                              void* d_out, int out_size)
{
    const float* x = (const float*)d_in[0];   // img_out  [16,3,512,512] f32
    const float* y = (const float*)d_in[1];   // img_target
    float* out = (float*)d_out;

    int planes = in_sizes[0] / PLANE;         // 48

    cudaFuncSetAttribute(ssim_kernel,
                         cudaFuncAttributeMaxDynamicSharedMemorySize,
                         SMEM_BYTES);

    dim3 grid(IMG / TW, IMG / TH, planes);    // (16, 8, 48)
    ssim_kernel<<<grid, NT, SMEM_BYTES>>>(x, y, out);
}

// round 11
// speedup vs baseline: 1.1266x; 1.1266x over previous
#include <cuda_runtime.h>

#define TW 32
#define TH 64
#define HALO 5
#define RW (TW + 2*HALO)      // 42
#define RH (TH + 2*HALO)      // 74
#define NT 512
#define IMG 512
#define PLANE (IMG*IMG)

#define SSIM_C1 0.0001f
#define SSIM_C2 0.0009f

// smem: float2 raw[RH*RW] (24864 B) + 4 hb planes [RH*TW] (37888 B) = 62752 B
#define RAW_N (RH*RW)
#define HB_N  (RH*TW)
#define SMEM_BYTES (RAW_N*8 + 4*HB_N*4)

// 11-tap gaussian, sigma=1.5, normalized; symmetric
__device__ __forceinline__ constexpr float wk(int k) {
    constexpr float W6[6] = { 0.00102838f, 0.00759876f, 0.03600077f,
                              0.10936078f, 0.21300553f, 0.26601171f };
    return W6[k < 6 ? k : 10 - k];
}

__global__ void __launch_bounds__(NT, 3)
ssim_kernel(const float* __restrict__ x, const float* __restrict__ y,
            float* __restrict__ out)
{
    extern __shared__ float smem[];
    float2* raw = (float2*)smem;            // RH*RW  {x,y}
    float*  hb  = smem + RAW_N*2;           // 4 planes: x, y, x2+y2, xy

    const int tid   = threadIdx.x;
    const int bx    = blockIdx.x;           // 0..15
    const int by    = blockIdx.y;           // 0..7
    const int plane = blockIdx.z;           // 0..47

    const float* __restrict__ xp = x + (size_t)plane * PLANE;
    const float* __restrict__ yp = y + (size_t)plane * PLANE;

    const int gx0 = bx * TW - HALO;
    const int gy0 = by * TH - HALO;

    const bool interior = (gx0 >= 0) & (gy0 >= 0) &
                          (gx0 + RW <= IMG) & (gy0 + RH <= IMG);

    // ---------------- Stage 1: gmem -> smem raw tile ----------------------
    if (interior) {
        // pair-granular: 21 column-pairs x 74 rows = 1554 tasks, divless walk
        int r = tid / 21;
        int c = tid - r * 21;                // pair index 0..20
        #pragma unroll 1
        while (r < RH) {
            const float* xq = xp + (gy0 + r) * IMG + gx0 + 2*c;
            const float* yq = yp + (gy0 + r) * IMG + gx0 + 2*c;
            float x0 = __ldg(xq);
            float x1 = __ldg(xq + 1);
            float y0 = __ldg(yq);
            float y1 = __ldg(yq + 1);
            *(float4*)&raw[r * RW + 2*c] = make_float4(x0, y0, x1, y1);
            r += 24; c += 8;                 // advance 512 = 24*21 + 8
            if (c >= 21) { c -= 21; r += 1; }
        }
    } else {
        #pragma unroll 1
        for (int i = tid; i < RAW_N; i += NT) {
            int r = i / RW;
            int c = i - r * RW;
            int gr = gy0 + r, gc = gx0 + c;
            float xv = 0.f, yv = 0.f;
            if ((unsigned)gr < (unsigned)IMG && (unsigned)gc < (unsigned)IMG) {
                int off = gr * IMG + gc;
                xv = __ldg(xp + off);
                yv = __ldg(yp + off);
            }
            raw[i] = make_float2(xv, yv);
        }
    }
    __syncthreads();

    // ---------------- Stage 2: horizontal 11-tap, 4-col register block ----
    // tasks: RH rows * 8 groups of 4 cols = 592
    for (int t = tid; t < RH*(TW/4); t += NT) {
        const int row = t >> 3;
        const int g   = (t & 7) * 4;
        const float4* rp4 = (const float4*)(raw + row * RW + g);  // 16B aligned

        float a0[4] = {0,0,0,0};   // hblur(x)
        float a1[4] = {0,0,0,0};   // hblur(y)
        float a2[4] = {0,0,0,0};   // hblur(x^2 + y^2)
        float a3[4] = {0,0,0,0};   // hblur(x*y)

        #pragma unroll
        for (int q = 0; q < 7; ++q) {        // 7 x LDS.128 = 14 taps
            float4 pr = rp4[q];              // {x0,y0,x1,y1} = taps 2q, 2q+1
            #pragma unroll
            for (int h = 0; h < 2; ++h) {
                const int p = 2*q + h;
                float vx = h ? pr.z : pr.x;
                float vy = h ? pr.w : pr.y;
                float s  = fmaf(vy, vy, vx * vx);
                float xy = vx * vy;
                #pragma unroll
                for (int i2 = 0; i2 < 4; ++i2) {
                    int k = p - i2;
                    if (k >= 0 && k <= 10) {
                        a0[i2] = fmaf(vx, wk(k), a0[i2]);
                        a1[i2] = fmaf(vy, wk(k), a1[i2]);
                        a2[i2] = fmaf(s,  wk(k), a2[i2]);
                        a3[i2] = fmaf(xy, wk(k), a3[i2]);
                    }
                }
            }
        }

        const int o = row * TW + g;
        *(float4*)&hb[0*HB_N + o] = make_float4(a0[0], a0[1], a0[2], a0[3]);
        *(float4*)&hb[1*HB_N + o] = make_float4(a1[0], a1[1], a1[2], a1[3]);
        *(float4*)&hb[2*HB_N + o] = make_float4(a2[0], a2[1], a2[2], a2[3]);
        *(float4*)&hb[3*HB_N + o] = make_float4(a3[0], a3[1], a3[2], a3[3]);
    }
    __syncthreads();

    // ---------------- Stage 3: vertical 11-tap, 8-row block on 256 threads
    // 256 tasks (32 cols x 8 segments); threads 256..511 exit. Same total
    // FFMA issue as 4-row on 512 threads, but 36% fewer LDS bytes.
    if (tid < 256) {
        const int col = tid & 31;
        const int r0  = (tid >> 5) * 8;     // 8 segments * 8 rows = 64

        float b0[8], b1[8], b2[8], b3[8];
        #pragma unroll
        for (int i2 = 0; i2 < 8; ++i2) {
            b0[i2] = 0.f; b1[i2] = 0.f; b2[i2] = 0.f; b3[i2] = 0.f;
        }

        const float* hcol = hb + col;
        #pragma unroll
        for (int p = 0; p < 18; ++p) {
            const int idx = (r0 + p) * TW;
            float h0 = hcol[0*HB_N + idx];
            float h1 = hcol[1*HB_N + idx];
            float h2 = hcol[2*HB_N + idx];
            float h3 = hcol[3*HB_N + idx];
            #pragma unroll
            for (int i2 = 0; i2 < 8; ++i2) {
                int k = p - i2;
                if (k >= 0 && k <= 10) {
                    b0[i2] = fmaf(h0, wk(k), b0[i2]);
                    b1[i2] = fmaf(h1, wk(k), b1[i2]);
                    b2[i2] = fmaf(h2, wk(k), b2[i2]);
                    b3[i2] = fmaf(h3, wk(k), b3[i2]);
                }
            }
        }

        float* op = out + (size_t)plane * PLANE
                        + (size_t)(by * TH + r0) * IMG
                        + bx * TW + col;

        #pragma unroll
        for (int i2 = 0; i2 < 8; ++i2) {
            float mu1  = b0[i2];
            float mu2  = b1[i2];
            float m12  = mu1 * mu2;
            float m11  = mu1 * mu1;
            float m22  = mu2 * mu2;
            float ssum = b2[i2] - m11 - m22;    // sigma1^2 + sigma2^2
            float s12  = b3[i2] - m12;
            float num = fmaf(2.f, m12, SSIM_C1) * fmaf(2.f, s12, SSIM_C2);
            float den = (m11 + m22 + SSIM_C1) * (ssum + SSIM_C2);
            op[(size_t)i2 * IMG] = __fdividef(num, den);
        }
    }
}

extern "C" void kernel_launch(void* const* d_in, const int* in_sizes, int n_in,
                              void* d_out, int out_size)
{
    const float* x = (const float*)d_in[0];   // img_out  [16,3,512,512] f32
    const float* y = (const float*)d_in[1];   // img_target
    float* out = (float*)d_out;

    int planes = in_sizes[0] / PLANE;         // 48

    cudaFuncSetAttribute(ssim_kernel,
                         cudaFuncAttributeMaxDynamicSharedMemorySize,
                         SMEM_BYTES);

    dim3 grid(IMG / TW, IMG / TH, planes);    // (16, 8, 48)
    ssim_kernel<<<grid, NT, SMEM_BYTES>>>(x, y, out);
}

// round 12
// speedup vs baseline: 1.1598x; 1.0295x over previous
#include <cuda_runtime.h>

#define TW 32
#define TH 64
#define HALO 5
#define RW (TW + 2*HALO)      // 42
#define RH (TH + 2*HALO)      // 74
#define NT 512
#define IMG 512
#define PLANE (IMG*IMG)

#define SSIM_C1 0.0001f
#define SSIM_C2 0.0009f

#define HBS 33                // hb row stride in float4 (padded: 4*33*4 banks -> odd phase step)
// smem: float2 raw[RH*RW] = 24864 B ; float4 hb[RH*HBS] = 39072 B ; total 63936 B
#define RAW_N (RH*RW)
#define SMEM_BYTES (RAW_N*8 + RH*HBS*16)

// 11-tap gaussian, sigma=1.5, normalized; symmetric
__device__ __forceinline__ constexpr float wk(int k) {
    constexpr float W6[6] = { 0.00102838f, 0.00759876f, 0.03600077f,
                              0.10936078f, 0.21300553f, 0.26601171f };
    return W6[k < 6 ? k : 10 - k];
}

__global__ void __launch_bounds__(NT, 3)
ssim_kernel(const float* __restrict__ x, const float* __restrict__ y,
            float* __restrict__ out)
{
    extern __shared__ float smem[];
    float2* raw = (float2*)smem;                 // RH*RW  {x,y}
    float4* hb4 = (float4*)(smem + RAW_N*2);     // RH*HBS {hx,hy,hs,hxy}

    const int tid   = threadIdx.x;
    const int bx    = blockIdx.x;                // 0..15
    const int by    = blockIdx.y;                // 0..7
    const int plane = blockIdx.z;                // 0..47

    const float* __restrict__ xp = x + (size_t)plane * PLANE;
    const float* __restrict__ yp = y + (size_t)plane * PLANE;

    const int gx0 = bx * TW - HALO;
    const int gy0 = by * TH - HALO;

    const bool interior = (gx0 >= 0) & (gy0 >= 0) &
                          (gx0 + RW <= IMG) & (gy0 + RH <= IMG);

    // ---------------- Stage 1: gmem -> smem raw tile ----------------------
    if (interior) {
        // pair-granular: 21 column-pairs x 74 rows = 1554 tasks, divless walk
        int r = tid / 21;
        int c = tid - r * 21;                // pair index 0..20
        #pragma unroll 1
        while (r < RH) {
            const float* xq = xp + (gy0 + r) * IMG + gx0 + 2*c;
            const float* yq = yp + (gy0 + r) * IMG + gx0 + 2*c;
            float x0 = __ldg(xq);
            float x1 = __ldg(xq + 1);
            float y0 = __ldg(yq);
            float y1 = __ldg(yq + 1);
            *(float4*)&raw[r * RW + 2*c] = make_float4(x0, y0, x1, y1);
            r += 24; c += 8;                 // advance 512 = 24*21 + 8
            if (c >= 21) { c -= 21; r += 1; }
        }
    } else {
        #pragma unroll 1
        for (int i = tid; i < RAW_N; i += NT) {
            int r = i / RW;
            int c = i - r * RW;
            int gr = gy0 + r, gc = gx0 + c;
            float xv = 0.f, yv = 0.f;
            if ((unsigned)gr < (unsigned)IMG && (unsigned)gc < (unsigned)IMG) {
                int off = gr * IMG + gc;
                xv = __ldg(xp + off);
                yv = __ldg(yp + off);
            }
            raw[i] = make_float2(xv, yv);
        }
    }
    __syncthreads();

    // ---------------- Stage 2: horizontal 11-tap, 4-col register block ----
    // tasks: 8 col-groups x 74 rows = 592; lanes map to consecutive ROWS
    // within a group -> conflict-free STS.128 / LDS.128 phases.
    #pragma unroll 1
    for (int t = tid; t < 8*RH; t += NT) {
        const int gq  = t / RH;              // column group 0..7
        const int row = t - gq * RH;         // 0..73
        const float4* rp4 = (const float4*)(raw + row * RW + 4*gq);

        float a0[4] = {0,0,0,0};   // hblur(x)
        float a1[4] = {0,0,0,0};   // hblur(y)
        float a2[4] = {0,0,0,0};   // hblur(x^2 + y^2)
        float a3[4] = {0,0,0,0};   // hblur(x*y)

        #pragma unroll
        for (int q = 0; q < 7; ++q) {        // 7 x LDS.128 = 14 taps
            float4 pr = rp4[q];              // {x0,y0,x1,y1} = taps 2q, 2q+1
            #pragma unroll
            for (int h = 0; h < 2; ++h) {
                const int p = 2*q + h;
                float vx = h ? pr.z : pr.x;
                float vy = h ? pr.w : pr.y;
                float s  = fmaf(vy, vy, vx * vx);
                float xy = vx * vy;
                #pragma unroll
                for (int i2 = 0; i2 < 4; ++i2) {
                    int k = p - i2;
                    if (k >= 0 && k <= 10) {
                        a0[i2] = fmaf(vx, wk(k), a0[i2]);
                        a1[i2] = fmaf(vy, wk(k), a1[i2]);
                        a2[i2] = fmaf(s,  wk(k), a2[i2]);
                        a3[i2] = fmaf(xy, wk(k), a3[i2]);
                    }
                }
            }
        }

        float4* hp = hb4 + row * HBS + 4*gq;
        #pragma unroll
        for (int i2 = 0; i2 < 4; ++i2)
            hp[i2] = make_float4(a0[i2], a1[i2], a2[i2], a3[i2]);
    }
    __syncthreads();

    // ---------------- Stage 3: vertical 11-tap, 4-row block, LDS.128 taps -
    {
        const int col = tid & 31;
        const int r0  = (tid >> 5) * 4;     // 16 segments * 4 rows = 64

        float b0[4] = {0,0,0,0}, b1[4] = {0,0,0,0},
              b2[4] = {0,0,0,0}, b3[4] = {0,0,0,0};

        const float4* hp = hb4 + r0 * HBS + col;
        #pragma unroll
        for (int p = 0; p < 14; ++p) {
            float4 h = hp[p * HBS];          // one LDS.128: all 4 quantities
            #pragma unroll
            for (int i2 = 0; i2 < 4; ++i2) {
                int k = p - i2;
                if (k >= 0 && k <= 10) {
                    b0[i2] = fmaf(h.x, wk(k), b0[i2]);
                    b1[i2] = fmaf(h.y, wk(k), b1[i2]);
                    b2[i2] = fmaf(h.z, wk(k), b2[i2]);
                    b3[i2] = fmaf(h.w, wk(k), b3[i2]);
                }
            }
        }

        float* op = out + (size_t)plane * PLANE
                        + (size_t)(by * TH + r0) * IMG
                        + bx * TW + col;

        #pragma unroll
        for (int i2 = 0; i2 < 4; ++i2) {
            float mu1  = b0[i2];
            float mu2  = b1[i2];
            float m12  = mu1 * mu2;
            float m11  = mu1 * mu1;
            float m22  = mu2 * mu2;
            float ssum = b2[i2] - m11 - m22;    // sigma1^2 + sigma2^2
            float s12  = b3[i2] - m12;
            float num = fmaf(2.f, m12, SSIM_C1) * fmaf(2.f, s12, SSIM_C2);
            float den = (m11 + m22 + SSIM_C1) * (ssum + SSIM_C2);
            op[(size_t)i2 * IMG] = __fdividef(num, den);
        }
    }
}

extern "C" void kernel_launch(void* const* d_in, const int* in_sizes, int n_in,
                              void* d_out, int out_size)
{
    const float* x = (const float*)d_in[0];   // img_out  [16,3,512,512] f32
    const float* y = (const float*)d_in[1];   // img_target
    float* out = (float*)d_out;

    int planes = in_sizes[0] / PLANE;         // 48

    cudaFuncSetAttribute(ssim_kernel,
                         cudaFuncAttributeMaxDynamicSharedMemorySize,
                         SMEM_BYTES);

    dim3 grid(IMG / TW, IMG / TH, planes);    // (16, 8, 48)
    ssim_kernel<<<grid, NT, SMEM_BYTES>>>(x, y, out);
}